// round 16
// baseline (speedup 1.0000x reference)
#include <cuda_runtime.h>
#include <cuda_bf16.h>
#include <cstdint>
#include <math.h>

#define Nb  8
#define Lq  2048
#define Sk  2048
#define Ein 1024
#define Dh  64

// Q projected, fp32 (source for 3-way split in attention)
__device__ float g_qh[Nb * Lq * Dh];
// K projected, 3 bf16 split planes; V projected, 2 bf16 split planes
__device__ __nv_bfloat16 g_khh[Nb * Sk * Dh];
__device__ __nv_bfloat16 g_khm[Nb * Sk * Dh];
__device__ __nv_bfloat16 g_khl[Nb * Sk * Dh];
__device__ __nv_bfloat16 g_vhh[Nb * Sk * Dh];
__device__ __nv_bfloat16 g_vhl[Nb * Sk * Dh];
// W split planes (built once by prep_w), layout [k][n]
__device__ __nv_bfloat16 g_Wh[3][Ein * Dh];
__device__ __nv_bfloat16 g_Wl[3][Ein * Dh];

// ---------------------------------------------------------------- helpers
__device__ __forceinline__ uint32_t smem_u32(const void* p) {
    uint32_t a;
    asm("{ .reg .u64 t; cvta.to.shared.u64 t, %1; cvt.u32.u64 %0, t; }"
        : "=r"(a) : "l"(p));
    return a;
}
__device__ __forceinline__ float ex2f(float x) {
    float y; asm("ex2.approx.f32 %0, %1;" : "=f"(y) : "f"(x)); return y;
}

#define LDMATRIX_X4(r0, r1, r2, r3, addr)                                   \
    asm volatile("ldmatrix.sync.aligned.m8n8.x4.shared.b16 {%0,%1,%2,%3}, [%4];" \
                 : "=r"(r0), "=r"(r1), "=r"(r2), "=r"(r3) : "r"(addr))
#define LDMATRIX_X4_T(r0, r1, r2, r3, addr)                                 \
    asm volatile("ldmatrix.sync.aligned.m8n8.x4.trans.shared.b16 {%0,%1,%2,%3}, [%4];" \
                 : "=r"(r0), "=r"(r1), "=r"(r2), "=r"(r3) : "r"(addr))

#define MMA_BF16(c, a, b0, b1)                                              \
    asm volatile("mma.sync.aligned.m16n8k16.row.col.f32.bf16.bf16.f32 "     \
                 "{%0,%1,%2,%3}, {%4,%5,%6,%7}, {%8,%9}, {%0,%1,%2,%3};"    \
                 : "+f"((c)[0]), "+f"((c)[1]), "+f"((c)[2]), "+f"((c)[3])   \
                 : "r"((a)[0]), "r"((a)[1]), "r"((a)[2]), "r"((a)[3]),      \
                   "r"(b0), "r"(b1))

#define CP_ASYNC16(dst, src)                                                \
    asm volatile("cp.async.cg.shared.global [%0], [%1], 16;"                \
                 :: "r"(dst), "l"(src) : "memory")
#define CP_COMMIT()  asm volatile("cp.async.commit_group;" ::: "memory")
#define CP_WAIT1()   asm volatile("cp.async.wait_group 1;" ::: "memory")
#define CP_WAIT3()   asm volatile("cp.async.wait_group 3;" ::: "memory")

#define PACK_BF16X2(u, x0, x1) \
    asm("cvt.rn.bf16x2.f32 %0, %1, %2;" : "=r"(u) : "f"(x1), "f"(x0))
#define PRMT_HI(u, a, b) \
    asm("prmt.b32 %0, %1, %2, 0x7632;" : "=r"(u) : "r"(a), "r"(b))
__device__ __forceinline__ float bf_lo(uint32_t u) { return __uint_as_float(u << 16); }
__device__ __forceinline__ float bf_hi(uint32_t u) { return __uint_as_float(u & 0xffff0000u); }

// ---------------------------------------------------------------- W prep: fp32 -> hi/lo bf16 planes
__global__ __launch_bounds__(256) void prep_w(const float* __restrict__ Wq,
                                              const float* __restrict__ Wk,
                                              const float* __restrict__ Wv) {
    const int y = blockIdx.y;
    const float* W = (y == 0) ? Wq : (y == 1) ? Wk : Wv;
    const int idx = blockIdx.x * 256 + threadIdx.x;       // pair index
    float2 p = ((const float2*)W)[idx];
    uint32_t h; PACK_BF16X2(h, p.x, p.y);
    float l0 = p.x - bf_lo(h), l1 = p.y - bf_hi(h);
    uint32_t l; PACK_BF16X2(l, l0, l1);
    ((uint32_t*)g_Wh[y])[idx] = h;
    ((uint32_t*)g_Wl[y])[idx] = l;
}

// ---------------------------------------------------------------- projection GEMM
// C[M,64] = A[M,1024] @ W[1024,64], bf16 split, 3 products (hh, hl, lh), fp32 accum.
// CTA 64x64, 4 warps (2m x 2n), warp tile 32x32, kb=32.
// Small CTA -> 4 CTAs/SM -> 4 independent barrier domains hide the
// LDG->convert->sync->mma chain across CTAs.
#define KB    32
#define APAD  40
#define WPAD  72

__global__ __launch_bounds__(128) void proj_mma(
    const float* __restrict__ q,  const float* __restrict__ kk_,
    const float* __restrict__ v,  float* __restrict__ qh) {

    __shared__ __nv_bfloat16 Asm[2][64][APAD];           // hi/lo planes (10240 B)
    __shared__ __nv_bfloat16 Wsm[2][2][KB][WPAD];        // [buf][plane][k][n] (18432 B)

    const int y = blockIdx.y;
    const float* A = (y == 0) ? q : (y == 1) ? kk_ : v;
    const __nv_bfloat16* Wh = g_Wh[y];
    const __nv_bfloat16* Wl = g_Wl[y];

    const int t    = threadIdx.x;
    const int lane = t & 31;
    const int warp = t >> 5;           // 0..3
    const int wm   = warp >> 1;        // 0..1
    const int wn   = warp & 1;
    const int m0   = blockIdx.x * 64;

    float c[2][4][4] = {};

    const uint32_t a_base = smem_u32(Asm);

    const int a_row  = wm * 32 + (lane & 7) + ((lane >> 3) & 1) * 8;
    const int a_colb = (lane >> 4) * 8;

    const int ar = t >> 1;             // A row 0..63
    const int ac = (t & 1) * 16;       // A col base
    const int wrow = t >> 2;           // W k row 0..31
    const int wc0  = (t & 3) * 8;      // W n base (2 chunks: wc0, wc0+32)

    float4 pa[4];
    auto load_regs = [&](int k0) {
        const float4* srcA = (const float4*)(A + (size_t)(m0 + ar) * Ein + k0 + ac);
#pragma unroll
        for (int i = 0; i < 4; i++) pa[i] = srcA[i];
    };
    auto conv_store = [&]() {
        uint32_t* d0 = (uint32_t*)&Asm[0][ar][ac];
        uint32_t* d1 = (uint32_t*)&Asm[1][ar][ac];
#pragma unroll
        for (int i = 0; i < 4; i++) {
            float4 p = pa[i];
            uint32_t x0 = __float_as_uint(p.x), x1 = __float_as_uint(p.y);
            uint32_t x2 = __float_as_uint(p.z), x3 = __float_as_uint(p.w);
            uint32_t h0, h1;
            PRMT_HI(h0, x0, x1);
            PRMT_HI(h1, x2, x3);
            float l0 = p.x - __uint_as_float(x0 & 0xffff0000u);
            float l1 = p.y - __uint_as_float(x1 & 0xffff0000u);
            float l2 = p.z - __uint_as_float(x2 & 0xffff0000u);
            float l3 = p.w - __uint_as_float(x3 & 0xffff0000u);
            uint32_t lo0; PACK_BF16X2(lo0, l0, l1);
            uint32_t lo1; PACK_BF16X2(lo1, l2, l3);
            d0[i * 2] = h0;  d0[i * 2 + 1] = h1;
            d1[i * 2] = lo0; d1[i * 2 + 1] = lo1;
        }
    };
    auto issue_w = [&](int k0, int b) {
#pragma unroll
        for (int j = 0; j < 2; j++) {
            int col = wc0 + j * 32;
            uint32_t dh = smem_u32(&Wsm[b][0][wrow][col]);
            uint32_t dl = smem_u32(&Wsm[b][1][wrow][col]);
            CP_ASYNC16(dh, (const void*)(Wh + (size_t)(k0 + wrow) * Dh + col));
            CP_ASYNC16(dl, (const void*)(Wl + (size_t)(k0 + wrow) * Dh + col));
        }
    };

    issue_w(0, 0); CP_COMMIT();
    load_regs(0);

    const int NIT = Ein / KB;   // 32
    for (int it = 0; it < NIT; it++) {
        const int buf = it & 1;
        if (it + 1 < NIT) { issue_w((it + 1) * KB, buf ^ 1); }
        CP_COMMIT();
        conv_store();
        if (it + 1 < NIT) load_regs((it + 1) * KB);
        CP_WAIT1();
        __syncthreads();

#pragma unroll
        for (int ks = 0; ks < 2; ks++) {
            uint32_t af[2][2][4];
            uint32_t bf[2][2][4];
#pragma unroll
            for (int s = 0; s < 2; s++) {
#pragma unroll
                for (int mi = 0; mi < 2; mi++) {
                    uint32_t addr = a_base + (uint32_t)(s * (64 * APAD) +
                        (a_row + mi * 16) * APAD + ks * 16 + a_colb) * 2u;
                    LDMATRIX_X4(af[s][mi][0], af[s][mi][1], af[s][mi][2], af[s][mi][3], addr);
                }
#pragma unroll
                for (int g = 0; g < 2; g++) {
                    uint32_t addr = smem_u32(
                        &Wsm[buf][s][ks * 16 + (lane & 15)][wn * 32 + g * 16 + ((lane >> 4) & 1) * 8]);
                    LDMATRIX_X4_T(bf[s][g][0], bf[s][g][1], bf[s][g][2], bf[s][g][3], addr);
                }
            }
            // products: (Ah,Wh), (Ah,Wl), (Al,Wh)  -- ll dropped
#pragma unroll
            for (int pr = 0; pr < 3; pr++) {
                const int sa = (pr == 2) ? 1 : 0;
                const int sb = (pr == 1) ? 1 : 0;
#pragma unroll
                for (int mi = 0; mi < 2; mi++)
#pragma unroll
                    for (int ni = 0; ni < 4; ni++) {
                        int g = ni >> 1, h = ni & 1;
                        MMA_BF16(c[mi][ni], af[sa][mi],
                                 bf[sb][g][h * 2], bf[sb][g][h * 2 + 1]);
                    }
            }
        }
        __syncthreads();
    }

    // ---- epilogue: Q -> fp32; K -> 3 bf16 planes; V -> 2 bf16 planes
#pragma unroll
    for (int mi = 0; mi < 2; mi++) {
#pragma unroll
        for (int ni = 0; ni < 4; ni++) {
            int row = m0 + wm * 32 + mi * 16 + (lane >> 2);
            int col = wn * 32 + ni * 8 + (lane & 3) * 2;
            if (y == 0) {
                float2 v0 = {c[mi][ni][0], c[mi][ni][1]};
                float2 v1 = {c[mi][ni][2], c[mi][ni][3]};
                *(float2*)(qh + (size_t)row * Dh + col)       = v0;
                *(float2*)(qh + (size_t)(row + 8) * Dh + col) = v1;
            } else {
#pragma unroll
                for (int rr = 0; rr < 2; rr++) {
                    float x0 = c[mi][ni][rr * 2], x1 = c[mi][ni][rr * 2 + 1];
                    size_t off = (size_t)(row + rr * 8) * Dh + col;
                    uint32_t u0; PACK_BF16X2(u0, x0, x1);
                    float r0 = x0 - bf_lo(u0), r1 = x1 - bf_hi(u0);
                    uint32_t u1; PACK_BF16X2(u1, r0, r1);
                    if (y == 1) {
                        float s0 = r0 - bf_lo(u1), s1 = r1 - bf_hi(u1);
                        uint32_t u2; PACK_BF16X2(u2, s0, s1);
                        *(uint32_t*)(g_khh + off) = u0;
                        *(uint32_t*)(g_khm + off) = u1;
                        *(uint32_t*)(g_khl + off) = u2;
                    } else {
                        *(uint32_t*)(g_vhh + off) = u0;
                        *(uint32_t*)(g_vhl + off) = u1;
                    }
                }
            }
        }
    }
}

// ---------------------------------------------------------------- attention (mma.sync)
// CTA = 128 q rows, 8 warps. Tiles diagonal-first (descending s0).
// Per tile: hi-only QK estimate -> warp skip vote (margin 24) -> full products.
// 4-stage cp.async pipeline, one commit group per iteration.
#define STRIDE 72
#define PLANE_B (64 * STRIDE * 2)
#define NPLANE 5           // Kh, Km, Kl, Vh, Vl
#define NBUF   4

__global__ __launch_bounds__(256) void attn_mma(float* __restrict__ out) {
    extern __shared__ uint8_t dsm[];
    const int t    = threadIdx.x;
    const int lane = t & 31;
    const int warp = t >> 5;
    const int n    = blockIdx.y;
    const int qt   = 15 - (int)blockIdx.x;
    const int q0   = qt * 128;
    const int ntile = qt * 2 + 2;

    const uint32_t smb = smem_u32(dsm);

    // ---- Q A-fragments: 3 splits x 4 k-steps x 4 regs
    uint32_t qa[3][4][4];
    const int rbase = q0 + warp * 16;
    {
        const float* qbase = g_qh + (size_t)n * Lq * Dh;
        const int r = rbase + (lane >> 2);
        const float sc = 11.54156036f;   // 8 * log2(e)
#pragma unroll
        for (int ks = 0; ks < 4; ks++)
#pragma unroll
            for (int hh = 0; hh < 2; hh++)
#pragma unroll
                for (int rr = 0; rr < 2; rr++) {
                    float2 x = *(const float2*)(qbase + (size_t)(r + rr * 8) * Dh +
                                                ks * 16 + (lane & 3) * 2 + hh * 8);
                    float x0 = x.x * sc, x1 = x.y * sc;
                    uint32_t u0; PACK_BF16X2(u0, x0, x1);
                    float r0 = x0 - bf_lo(u0), r1 = x1 - bf_hi(u0);
                    uint32_t u1; PACK_BF16X2(u1, r0, r1);
                    float s0 = r0 - bf_lo(u1), s1 = r1 - bf_hi(u1);
                    uint32_t u2; PACK_BF16X2(u2, s0, s1);
                    int ai = rr + hh * 2;
                    qa[0][ks][ai] = u0; qa[1][ks][ai] = u1; qa[2][ks][ai] = u2;
                }
    }

    const __nv_bfloat16* gp[NPLANE] = {
        g_khh + (size_t)n * Sk * Dh, g_khm + (size_t)n * Sk * Dh,
        g_khl + (size_t)n * Sk * Dh, g_vhh + (size_t)n * Sk * Dh,
        g_vhl + (size_t)n * Sk * Dh };

    // reversed order: tile index i -> s0 = (ntile-1-i)*64 (diagonal first)
    auto issue_tile = [&](int i) {
        const int b  = i & (NBUF - 1);
        const int s0 = (ntile - 1 - i) * 64;
#pragma unroll
        for (int p = 0; p < NPLANE; p++) {
#pragma unroll
            for (int j = 0; j < 2; j++) {
                int chunk = t + j * 256;
                int row = chunk >> 3, c16 = chunk & 7;
                uint32_t dst = smb + (uint32_t)((b * NPLANE + p) * PLANE_B) +
                               (uint32_t)(row * STRIDE * 2 + c16 * 16);
                CP_ASYNC16(dst, (const void*)(gp[p] + ((size_t)(s0 + row) * Dh + c16 * 8)));
            }
        }
    };

    // prologue: 3 tiles in flight, one commit group each
#pragma unroll
    for (int i = 0; i < 3; i++) {
        if (i < ntile) issue_tile(i);
        CP_COMMIT();
    }

    float O[8][4] = {};
    float m0 = -1e30f, m1 = -1e30f, l0 = 0.0f, l1 = 0.0f;

    for (int tile = 0; tile < ntile; tile++) {
        if (tile + 3 < ntile) issue_tile(tile + 3);
        CP_COMMIT();             // exactly one group per iteration
        CP_WAIT3();              // tile's group complete
        __syncthreads();

        const int b = tile & (NBUF - 1);
        const uint32_t kh_p = smb + (uint32_t)((b * NPLANE + 0) * PLANE_B);
        const uint32_t km_p = smb + (uint32_t)((b * NPLANE + 1) * PLANE_B);
        const uint32_t kl_p = smb + (uint32_t)((b * NPLANE + 2) * PLANE_B);
        const uint32_t vh_p = smb + (uint32_t)((b * NPLANE + 3) * PLANE_B);
        const uint32_t vl_p = smb + (uint32_t)((b * NPLANE + 4) * PLANE_B);
        const int s0 = (ntile - 1 - tile) * 64;

        const uint32_t koff =
            (uint32_t)(((lane & 7) + (lane >> 4) * 8) * STRIDE + ((lane >> 3) & 1) * 8) * 2u;

        // ---- estimate: S_hi = q0 . kh only
        float S[8][4] = {};
#pragma unroll
        for (int ks = 0; ks < 4; ks++)
#pragma unroll
            for (int sg = 0; sg < 4; sg++) {
                uint32_t base = (uint32_t)(sg * 16 * STRIDE + ks * 16) * 2u + koff;
                uint32_t kh[4];
                LDMATRIX_X4(kh[0], kh[1], kh[2], kh[3], kh_p + base);
                MMA_BF16(S[2 * sg],     qa[0][ks], kh[0], kh[1]);
                MMA_BF16(S[2 * sg + 1], qa[0][ks], kh[2], kh[3]);
            }

        // ---- causal mask
        if (s0 + 63 > rbase) {
            const int rl0 = rbase + (lane >> 2);
#pragma unroll
            for (int nt = 0; nt < 8; nt++) {
                int cl = s0 + nt * 8 + (lane & 3) * 2;
#pragma unroll
                for (int e = 0; e < 4; e++) {
                    int col = cl + (e & 1);
                    int rl  = rl0 + (e >> 1) * 8;
                    if (col > rl) S[nt][e] = -1e30f;
                }
            }
        }

        // ---- per-row tile max + warp skip vote (margin 24 = 20 cutoff + est err)
        float tr0 = S[0][0], tr1 = S[0][2];
#pragma unroll
        for (int nt = 0; nt < 8; nt++) {
            tr0 = fmaxf(tr0, fmaxf(S[nt][0], S[nt][1]));
            tr1 = fmaxf(tr1, fmaxf(S[nt][2], S[nt][3]));
        }
        tr0 = fmaxf(tr0, __shfl_xor_sync(0xffffffffu, tr0, 1));
        tr0 = fmaxf(tr0, __shfl_xor_sync(0xffffffffu, tr0, 2));
        tr1 = fmaxf(tr1, __shfl_xor_sync(0xffffffffu, tr1, 1));
        tr1 = fmaxf(tr1, __shfl_xor_sync(0xffffffffu, tr1, 2));

        bool skip = ((tr0 < m0 - 24.0f) && (tr1 < m1 - 24.0f)) || (tr0 < -1e29f);
        if (!__all_sync(0xffffffffu, skip)) {
            // ---- full QK: remaining 5 split products
#pragma unroll
            for (int ks = 0; ks < 4; ks++)
#pragma unroll
                for (int sg = 0; sg < 4; sg++) {
                    uint32_t base = (uint32_t)(sg * 16 * STRIDE + ks * 16) * 2u + koff;
                    uint32_t kh[4], km[4], kl[4];
                    LDMATRIX_X4(kh[0], kh[1], kh[2], kh[3], kh_p + base);
                    LDMATRIX_X4(km[0], km[1], km[2], km[3], km_p + base);
                    LDMATRIX_X4(kl[0], kl[1], kl[2], kl[3], kl_p + base);
                    MMA_BF16(S[2 * sg],     qa[0][ks], km[0], km[1]);
                    MMA_BF16(S[2 * sg + 1], qa[0][ks], km[2], km[3]);
                    MMA_BF16(S[2 * sg],     qa[1][ks], kh[0], kh[1]);
                    MMA_BF16(S[2 * sg + 1], qa[1][ks], kh[2], kh[3]);
                    MMA_BF16(S[2 * sg],     qa[1][ks], km[0], km[1]);
                    MMA_BF16(S[2 * sg + 1], qa[1][ks], km[2], km[3]);
                    MMA_BF16(S[2 * sg],     qa[2][ks], kh[0], kh[1]);
                    MMA_BF16(S[2 * sg + 1], qa[2][ks], kh[2], kh[3]);
                    MMA_BF16(S[2 * sg],     qa[0][ks], kl[0], kl[1]);
                    MMA_BF16(S[2 * sg + 1], qa[0][ks], kl[2], kl[3]);
                }

            float mn0 = fmaxf(m0, tr0), mn1 = fmaxf(m1, tr1);
            float f0 = ex2f(m0 - mn0), f1 = ex2f(m1 - mn1);
            m0 = mn0; m1 = mn1;
            l0 *= f0;  l1 *= f1;
#pragma unroll
            for (int nt = 0; nt < 8; nt++) {
                O[nt][0] *= f0; O[nt][1] *= f0;
                O[nt][2] *= f1; O[nt][3] *= f1;
            }
#pragma unroll
            for (int nt = 0; nt < 8; nt++) {
                float p0 = ex2f(S[nt][0] - mn0);
                float p1 = ex2f(S[nt][1] - mn0);
                float p2 = ex2f(S[nt][2] - mn1);
                float p3 = ex2f(S[nt][3] - mn1);
                l0 += p0 + p1; l1 += p2 + p3;
                S[nt][0] = p0; S[nt][1] = p1; S[nt][2] = p2; S[nt][3] = p3;
            }
            // ---- PV: P 2-split x V 2-split, 3 products
            const uint32_t voff = (uint32_t)((lane & 15) * STRIDE + (lane >> 4) * 8) * 2u;
#pragma unroll
            for (int ks = 0; ks < 4; ks++) {
                uint32_t ah[4], al[4];
#pragma unroll
                for (int i = 0; i < 2; i++) {
                    int nt = 2 * ks + i;
                    uint32_t uh0; PACK_BF16X2(uh0, S[nt][0], S[nt][1]);
                    uint32_t uh1; PACK_BF16X2(uh1, S[nt][2], S[nt][3]);
                    float a0 = S[nt][0] - bf_lo(uh0), a1 = S[nt][1] - bf_hi(uh0);
                    float a2 = S[nt][2] - bf_lo(uh1), a3 = S[nt][3] - bf_hi(uh1);
                    uint32_t ul0; PACK_BF16X2(ul0, a0, a1);
                    uint32_t ul1; PACK_BF16X2(ul1, a2, a3);
                    ah[2 * i] = uh0; ah[2 * i + 1] = uh1;
                    al[2 * i] = ul0; al[2 * i + 1] = ul1;
                }
#pragma unroll
                for (int dg = 0; dg < 4; dg++) {
                    uint32_t base = (uint32_t)(ks * 16 * STRIDE + dg * 16) * 2u + voff;
                    uint32_t vh[4], vl[4];
                    LDMATRIX_X4_T(vh[0], vh[1], vh[2], vh[3], vh_p + base);
                    LDMATRIX_X4_T(vl[0], vl[1], vl[2], vl[3], vl_p + base);
                    MMA_BF16(O[2 * dg],     ah, vh[0], vh[1]);
                    MMA_BF16(O[2 * dg + 1], ah, vh[2], vh[3]);
                    MMA_BF16(O[2 * dg],     al, vh[0], vh[1]);
                    MMA_BF16(O[2 * dg + 1], al, vh[2], vh[3]);
                    MMA_BF16(O[2 * dg],     ah, vl[0], vl[1]);
                    MMA_BF16(O[2 * dg + 1], ah, vl[2], vl[3]);
                }
            }
        }
        __syncthreads();
    }

    // ---- epilogue
    l0 += __shfl_xor_sync(0xffffffffu, l0, 1);
    l0 += __shfl_xor_sync(0xffffffffu, l0, 2);
    l1 += __shfl_xor_sync(0xffffffffu, l1, 1);
    l1 += __shfl_xor_sync(0xffffffffu, l1, 2);
    float inv0 = 1.0f / l0, inv1 = 1.0f / l1;

    const size_t gr0 = (size_t)n * Lq + rbase + (lane >> 2);
#pragma unroll
    for (int nt = 0; nt < 8; nt++) {
        int col = nt * 8 + (lane & 3) * 2;
        float2 v0 = {O[nt][0] * inv0, O[nt][1] * inv0};
        float2 v1 = {O[nt][2] * inv1, O[nt][3] * inv1};
        *(float2*)(out + gr0 * Dh + col)       = v0;
        *(float2*)(out + (gr0 + 8) * Dh + col) = v1;
    }
}

extern "C" void kernel_launch(void* const* d_in, const int* in_sizes, int n_in,
                              void* d_out, int out_size) {
    const float* q  = (const float*)d_in[0];
    const float* k  = (const float*)d_in[1];
    const float* v  = (const float*)d_in[2];
    const float* Wq = (const float*)d_in[3];
    const float* Wk = (const float*)d_in[4];
    const float* Wv = (const float*)d_in[5];
    float* out = (float*)d_out;

    float* qh;
    cudaGetSymbolAddress((void**)&qh, g_qh);

    const int smem_attn = NBUF * NPLANE * PLANE_B;   // 184320 B
    cudaFuncSetAttribute(attn_mma, cudaFuncAttributeMaxDynamicSharedMemorySize, smem_attn);

    dim3 wgrid((Ein * Dh / 2) / 256, 3);
    prep_w<<<wgrid, 256>>>(Wq, Wk, Wv);

    dim3 pgrid((Nb * Lq) / 64, 3);
    proj_mma<<<pgrid, 128>>>(q, k, v, qh);

    dim3 grid(16, Nb);
    attn_mma<<<grid, 256, smem_attn>>>(out);
}

// round 17
// speedup vs baseline: 1.7709x; 1.7709x over previous
#include <cuda_runtime.h>
#include <cuda_bf16.h>
#include <cstdint>
#include <math.h>

#define Nb  8
#define Lq  2048
#define Sk  2048
#define Ein 1024
#define Dh  64

// Q projected, fp32 (source for 2-way split in attention)
__device__ float g_qh[Nb * Lq * Dh];
// K projected, 2 bf16 split planes; V projected, 2 bf16 split planes
__device__ __nv_bfloat16 g_khh[Nb * Sk * Dh];
__device__ __nv_bfloat16 g_khm[Nb * Sk * Dh];
__device__ __nv_bfloat16 g_vhh[Nb * Sk * Dh];
__device__ __nv_bfloat16 g_vhl[Nb * Sk * Dh];
// W split planes (built once by prep_w), layout [k][n]
__device__ __nv_bfloat16 g_Wh[3][Ein * Dh];
__device__ __nv_bfloat16 g_Wl[3][Ein * Dh];

// ---------------------------------------------------------------- helpers
__device__ __forceinline__ uint32_t smem_u32(const void* p) {
    uint32_t a;
    asm("{ .reg .u64 t; cvta.to.shared.u64 t, %1; cvt.u32.u64 %0, t; }"
        : "=r"(a) : "l"(p));
    return a;
}
__device__ __forceinline__ float ex2f(float x) {
    float y; asm("ex2.approx.f32 %0, %1;" : "=f"(y) : "f"(x)); return y;
}

#define LDMATRIX_X4(r0, r1, r2, r3, addr)                                   \
    asm volatile("ldmatrix.sync.aligned.m8n8.x4.shared.b16 {%0,%1,%2,%3}, [%4];" \
                 : "=r"(r0), "=r"(r1), "=r"(r2), "=r"(r3) : "r"(addr))
#define LDMATRIX_X4_T(r0, r1, r2, r3, addr)                                 \
    asm volatile("ldmatrix.sync.aligned.m8n8.x4.trans.shared.b16 {%0,%1,%2,%3}, [%4];" \
                 : "=r"(r0), "=r"(r1), "=r"(r2), "=r"(r3) : "r"(addr))

#define MMA_BF16(c, a, b0, b1)                                              \
    asm volatile("mma.sync.aligned.m16n8k16.row.col.f32.bf16.bf16.f32 "     \
                 "{%0,%1,%2,%3}, {%4,%5,%6,%7}, {%8,%9}, {%0,%1,%2,%3};"    \
                 : "+f"((c)[0]), "+f"((c)[1]), "+f"((c)[2]), "+f"((c)[3])   \
                 : "r"((a)[0]), "r"((a)[1]), "r"((a)[2]), "r"((a)[3]),      \
                   "r"(b0), "r"(b1))

#define CP_ASYNC16(dst, src)                                                \
    asm volatile("cp.async.cg.shared.global [%0], [%1], 16;"                \
                 :: "r"(dst), "l"(src) : "memory")
#define CP_COMMIT()  asm volatile("cp.async.commit_group;" ::: "memory")
#define CP_WAIT1()   asm volatile("cp.async.wait_group 1;" ::: "memory")
#define CP_WAIT3()   asm volatile("cp.async.wait_group 3;" ::: "memory")

#define PACK_BF16X2(u, x0, x1) \
    asm("cvt.rn.bf16x2.f32 %0, %1, %2;" : "=r"(u) : "f"(x1), "f"(x0))
#define PRMT_HI(u, a, b) \
    asm("prmt.b32 %0, %1, %2, 0x7632;" : "=r"(u) : "r"(a), "r"(b))
__device__ __forceinline__ float bf_lo(uint32_t u) { return __uint_as_float(u << 16); }
__device__ __forceinline__ float bf_hi(uint32_t u) { return __uint_as_float(u & 0xffff0000u); }

// ---------------------------------------------------------------- W prep: fp32 -> hi/lo bf16 planes
__global__ __launch_bounds__(256) void prep_w(const float* __restrict__ Wq,
                                              const float* __restrict__ Wk,
                                              const float* __restrict__ Wv) {
    const int y = blockIdx.y;
    const float* W = (y == 0) ? Wq : (y == 1) ? Wk : Wv;
    const int idx = blockIdx.x * 256 + threadIdx.x;       // pair index
    float2 p = ((const float2*)W)[idx];
    uint32_t h; PACK_BF16X2(h, p.x, p.y);
    float l0 = p.x - bf_lo(h), l1 = p.y - bf_hi(h);
    uint32_t l; PACK_BF16X2(l, l0, l1);
    ((uint32_t*)g_Wh[y])[idx] = h;
    ((uint32_t*)g_Wl[y])[idx] = l;
}

// ---------------------------------------------------------------- projection GEMM
// C[M,64] = A[M,1024] @ W[1024,64], bf16 split, 3 products (hh, hl, lh), fp32 accum.
// CTA 128x64, 8 warps (4m x 2n), warp tile 32x32, kb=32.  (R10 structure)
#define KB    32
#define APAD  40
#define WPAD  72

__global__ __launch_bounds__(256) void proj_mma(
    const float* __restrict__ q,  const float* __restrict__ kk_,
    const float* __restrict__ v,  float* __restrict__ qh) {

    __shared__ __nv_bfloat16 Asm[2][128][APAD];          // hi/lo planes
    __shared__ __nv_bfloat16 Wsm[2][2][KB][WPAD];        // [buf][plane][k][n]

    const int y = blockIdx.y;
    const float* A = (y == 0) ? q : (y == 1) ? kk_ : v;
    const __nv_bfloat16* Wh = g_Wh[y];
    const __nv_bfloat16* Wl = g_Wl[y];

    const int t    = threadIdx.x;
    const int lane = t & 31;
    const int warp = t >> 5;
    const int wm   = warp >> 1;
    const int wn   = warp & 1;
    const int m0   = blockIdx.x * 128;

    float c[2][4][4] = {};

    const uint32_t a_base = smem_u32(Asm);

    const int a_row  = wm * 32 + (lane & 7) + ((lane >> 3) & 1) * 8;
    const int a_colb = (lane >> 4) * 8;

    const int ar = t >> 1;             // A row 0..127
    const int ac = (t & 1) * 16;       // A col base
    const int wrow = t >> 3;           // W k row 0..31
    const int wn16 = (t & 7) * 8;      // W n base

    float4 pa[4];
    auto load_regs = [&](int k0) {
        const float4* srcA = (const float4*)(A + (size_t)(m0 + ar) * Ein + k0 + ac);
#pragma unroll
        for (int i = 0; i < 4; i++) pa[i] = srcA[i];
    };
    auto conv_store = [&]() {
        uint32_t* d0 = (uint32_t*)&Asm[0][ar][ac];
        uint32_t* d1 = (uint32_t*)&Asm[1][ar][ac];
#pragma unroll
        for (int i = 0; i < 4; i++) {
            float4 p = pa[i];
            uint32_t x0 = __float_as_uint(p.x), x1 = __float_as_uint(p.y);
            uint32_t x2 = __float_as_uint(p.z), x3 = __float_as_uint(p.w);
            uint32_t h0, h1;
            PRMT_HI(h0, x0, x1);
            PRMT_HI(h1, x2, x3);
            float l0 = p.x - __uint_as_float(x0 & 0xffff0000u);
            float l1 = p.y - __uint_as_float(x1 & 0xffff0000u);
            float l2 = p.z - __uint_as_float(x2 & 0xffff0000u);
            float l3 = p.w - __uint_as_float(x3 & 0xffff0000u);
            uint32_t lo0; PACK_BF16X2(lo0, l0, l1);
            uint32_t lo1; PACK_BF16X2(lo1, l2, l3);
            d0[i * 2] = h0;  d0[i * 2 + 1] = h1;
            d1[i * 2] = lo0; d1[i * 2 + 1] = lo1;
        }
    };
    auto issue_w = [&](int k0, int b) {
        uint32_t dh = smem_u32(&Wsm[b][0][wrow][wn16]);
        uint32_t dl = smem_u32(&Wsm[b][1][wrow][wn16]);
        CP_ASYNC16(dh, (const void*)(Wh + (size_t)(k0 + wrow) * Dh + wn16));
        CP_ASYNC16(dl, (const void*)(Wl + (size_t)(k0 + wrow) * Dh + wn16));
    };

    issue_w(0, 0); CP_COMMIT();
    load_regs(0);

    const int NIT = Ein / KB;   // 32
    for (int it = 0; it < NIT; it++) {
        const int buf = it & 1;
        if (it + 1 < NIT) { issue_w((it + 1) * KB, buf ^ 1); }
        CP_COMMIT();
        conv_store();
        if (it + 1 < NIT) load_regs((it + 1) * KB);
        CP_WAIT1();
        __syncthreads();

#pragma unroll
        for (int ks = 0; ks < 2; ks++) {
            uint32_t af[2][2][4];
            uint32_t bf[2][2][4];
#pragma unroll
            for (int s = 0; s < 2; s++) {
#pragma unroll
                for (int mi = 0; mi < 2; mi++) {
                    uint32_t addr = a_base + (uint32_t)(s * (128 * APAD) +
                        (a_row + mi * 16) * APAD + ks * 16 + a_colb) * 2u;
                    LDMATRIX_X4(af[s][mi][0], af[s][mi][1], af[s][mi][2], af[s][mi][3], addr);
                }
#pragma unroll
                for (int g = 0; g < 2; g++) {
                    uint32_t addr = smem_u32(
                        &Wsm[buf][s][ks * 16 + (lane & 15)][wn * 32 + g * 16 + ((lane >> 4) & 1) * 8]);
                    LDMATRIX_X4_T(bf[s][g][0], bf[s][g][1], bf[s][g][2], bf[s][g][3], addr);
                }
            }
            // products: (Ah,Wh), (Ah,Wl), (Al,Wh)  -- ll dropped
#pragma unroll
            for (int pr = 0; pr < 3; pr++) {
                const int sa = (pr == 2) ? 1 : 0;
                const int sb = (pr == 1) ? 1 : 0;
#pragma unroll
                for (int mi = 0; mi < 2; mi++)
#pragma unroll
                    for (int ni = 0; ni < 4; ni++) {
                        int g = ni >> 1, h = ni & 1;
                        MMA_BF16(c[mi][ni], af[sa][mi],
                                 bf[sb][g][h * 2], bf[sb][g][h * 2 + 1]);
                    }
            }
        }
        __syncthreads();
    }

    // ---- epilogue: Q -> fp32; K -> 2 bf16 planes; V -> 2 bf16 planes
#pragma unroll
    for (int mi = 0; mi < 2; mi++) {
#pragma unroll
        for (int ni = 0; ni < 4; ni++) {
            int row = m0 + wm * 32 + mi * 16 + (lane >> 2);
            int col = wn * 32 + ni * 8 + (lane & 3) * 2;
            if (y == 0) {
                float2 v0 = {c[mi][ni][0], c[mi][ni][1]};
                float2 v1 = {c[mi][ni][2], c[mi][ni][3]};
                *(float2*)(qh + (size_t)row * Dh + col)       = v0;
                *(float2*)(qh + (size_t)(row + 8) * Dh + col) = v1;
            } else {
#pragma unroll
                for (int rr = 0; rr < 2; rr++) {
                    float x0 = c[mi][ni][rr * 2], x1 = c[mi][ni][rr * 2 + 1];
                    size_t off = (size_t)(row + rr * 8) * Dh + col;
                    uint32_t u0; PACK_BF16X2(u0, x0, x1);
                    float r0 = x0 - bf_lo(u0), r1 = x1 - bf_hi(u0);
                    uint32_t u1; PACK_BF16X2(u1, r0, r1);
                    if (y == 1) {
                        *(uint32_t*)(g_khh + off) = u0;
                        *(uint32_t*)(g_khm + off) = u1;
                    } else {
                        *(uint32_t*)(g_vhh + off) = u0;
                        *(uint32_t*)(g_vhl + off) = u1;
                    }
                }
            }
        }
    }
}

// ---------------------------------------------------------------- attention (mma.sync)
// CTA = 128 q rows, 8 warps. Tiles diagonal-first (descending s0).
// Q 2-split x K 2-split: est = q0.kh; full path adds q0.km + q1.kh.
// 4-stage cp.async pipeline (one commit group per iteration), 4 planes.
#define STRIDE 72
#define PLANE_B (64 * STRIDE * 2)
#define NPLANE 4           // Kh, Km, Vh, Vl
#define NBUF   4

__global__ __launch_bounds__(256) void attn_mma(float* __restrict__ out) {
    extern __shared__ uint8_t dsm[];
    const int t    = threadIdx.x;
    const int lane = t & 31;
    const int warp = t >> 5;
    const int n    = blockIdx.y;
    const int qt   = 15 - (int)blockIdx.x;
    const int q0   = qt * 128;
    const int ntile = qt * 2 + 2;

    const uint32_t smb = smem_u32(dsm);

    // ---- Q A-fragments: 2 splits x 4 k-steps x 4 regs
    uint32_t qa[2][4][4];
    const int rbase = q0 + warp * 16;
    {
        const float* qbase = g_qh + (size_t)n * Lq * Dh;
        const int r = rbase + (lane >> 2);
        const float sc = 11.54156036f;   // 8 * log2(e)
#pragma unroll
        for (int ks = 0; ks < 4; ks++)
#pragma unroll
            for (int hh = 0; hh < 2; hh++)
#pragma unroll
                for (int rr = 0; rr < 2; rr++) {
                    float2 x = *(const float2*)(qbase + (size_t)(r + rr * 8) * Dh +
                                                ks * 16 + (lane & 3) * 2 + hh * 8);
                    float x0 = x.x * sc, x1 = x.y * sc;
                    uint32_t u0; PACK_BF16X2(u0, x0, x1);
                    float r0 = x0 - bf_lo(u0), r1 = x1 - bf_hi(u0);
                    uint32_t u1; PACK_BF16X2(u1, r0, r1);
                    int ai = rr + hh * 2;
                    qa[0][ks][ai] = u0; qa[1][ks][ai] = u1;
                }
    }

    const __nv_bfloat16* gp[NPLANE] = {
        g_khh + (size_t)n * Sk * Dh, g_khm + (size_t)n * Sk * Dh,
        g_vhh + (size_t)n * Sk * Dh, g_vhl + (size_t)n * Sk * Dh };

    // reversed order: tile index i -> s0 = (ntile-1-i)*64 (diagonal first)
    auto issue_tile = [&](int i) {
        const int b  = i & (NBUF - 1);
        const int s0 = (ntile - 1 - i) * 64;
#pragma unroll
        for (int p = 0; p < NPLANE; p++) {
#pragma unroll
            for (int j = 0; j < 2; j++) {
                int chunk = t + j * 256;
                int row = chunk >> 3, c16 = chunk & 7;
                uint32_t dst = smb + (uint32_t)((b * NPLANE + p) * PLANE_B) +
                               (uint32_t)(row * STRIDE * 2 + c16 * 16);
                CP_ASYNC16(dst, (const void*)(gp[p] + ((size_t)(s0 + row) * Dh + c16 * 8)));
            }
        }
    };

    // prologue: 3 tiles in flight, one commit group each
#pragma unroll
    for (int i = 0; i < 3; i++) {
        if (i < ntile) issue_tile(i);
        CP_COMMIT();
    }

    float O[8][4] = {};
    float m0 = -1e30f, m1 = -1e30f, l0 = 0.0f, l1 = 0.0f;

    for (int tile = 0; tile < ntile; tile++) {
        if (tile + 3 < ntile) issue_tile(tile + 3);
        CP_COMMIT();             // exactly one group per iteration
        CP_WAIT3();              // tile's group complete
        __syncthreads();

        const int b = tile & (NBUF - 1);
        const uint32_t kh_p = smb + (uint32_t)((b * NPLANE + 0) * PLANE_B);
        const uint32_t km_p = smb + (uint32_t)((b * NPLANE + 1) * PLANE_B);
        const uint32_t vh_p = smb + (uint32_t)((b * NPLANE + 2) * PLANE_B);
        const uint32_t vl_p = smb + (uint32_t)((b * NPLANE + 3) * PLANE_B);
        const int s0 = (ntile - 1 - tile) * 64;

        const uint32_t koff =
            (uint32_t)(((lane & 7) + (lane >> 4) * 8) * STRIDE + ((lane >> 3) & 1) * 8) * 2u;

        // ---- estimate: S_hi = q0 . kh only
        float S[8][4] = {};
#pragma unroll
        for (int ks = 0; ks < 4; ks++)
#pragma unroll
            for (int sg = 0; sg < 4; sg++) {
                uint32_t base = (uint32_t)(sg * 16 * STRIDE + ks * 16) * 2u + koff;
                uint32_t kh[4];
                LDMATRIX_X4(kh[0], kh[1], kh[2], kh[3], kh_p + base);
                MMA_BF16(S[2 * sg],     qa[0][ks], kh[0], kh[1]);
                MMA_BF16(S[2 * sg + 1], qa[0][ks], kh[2], kh[3]);
            }

        // ---- causal mask
        if (s0 + 63 > rbase) {
            const int rl0 = rbase + (lane >> 2);
#pragma unroll
            for (int nt = 0; nt < 8; nt++) {
                int cl = s0 + nt * 8 + (lane & 3) * 2;
#pragma unroll
                for (int e = 0; e < 4; e++) {
                    int col = cl + (e & 1);
                    int rl  = rl0 + (e >> 1) * 8;
                    if (col > rl) S[nt][e] = -1e30f;
                }
            }
        }

        // ---- per-row tile max + warp skip vote (margin 24 = 20 cutoff + est err)
        float tr0 = S[0][0], tr1 = S[0][2];
#pragma unroll
        for (int nt = 0; nt < 8; nt++) {
            tr0 = fmaxf(tr0, fmaxf(S[nt][0], S[nt][1]));
            tr1 = fmaxf(tr1, fmaxf(S[nt][2], S[nt][3]));
        }
        tr0 = fmaxf(tr0, __shfl_xor_sync(0xffffffffu, tr0, 1));
        tr0 = fmaxf(tr0, __shfl_xor_sync(0xffffffffu, tr0, 2));
        tr1 = fmaxf(tr1, __shfl_xor_sync(0xffffffffu, tr1, 1));
        tr1 = fmaxf(tr1, __shfl_xor_sync(0xffffffffu, tr1, 2));

        bool skip = ((tr0 < m0 - 24.0f) && (tr1 < m1 - 24.0f)) || (tr0 < -1e29f);
        if (!__all_sync(0xffffffffu, skip)) {
            // ---- full QK: add q0.km + q1.kh
#pragma unroll
            for (int ks = 0; ks < 4; ks++)
#pragma unroll
                for (int sg = 0; sg < 4; sg++) {
                    uint32_t base = (uint32_t)(sg * 16 * STRIDE + ks * 16) * 2u + koff;
                    uint32_t kh[4], km[4];
                    LDMATRIX_X4(kh[0], kh[1], kh[2], kh[3], kh_p + base);
                    LDMATRIX_X4(km[0], km[1], km[2], km[3], km_p + base);
                    MMA_BF16(S[2 * sg],     qa[0][ks], km[0], km[1]);
                    MMA_BF16(S[2 * sg + 1], qa[0][ks], km[2], km[3]);
                    MMA_BF16(S[2 * sg],     qa[1][ks], kh[0], kh[1]);
                    MMA_BF16(S[2 * sg + 1], qa[1][ks], kh[2], kh[3]);
                }

            float mn0 = fmaxf(m0, tr0), mn1 = fmaxf(m1, tr1);
            float f0 = ex2f(m0 - mn0), f1 = ex2f(m1 - mn1);
            m0 = mn0; m1 = mn1;
            l0 *= f0;  l1 *= f1;
#pragma unroll
            for (int nt = 0; nt < 8; nt++) {
                O[nt][0] *= f0; O[nt][1] *= f0;
                O[nt][2] *= f1; O[nt][3] *= f1;
            }
#pragma unroll
            for (int nt = 0; nt < 8; nt++) {
                float p0 = ex2f(S[nt][0] - mn0);
                float p1 = ex2f(S[nt][1] - mn0);
                float p2 = ex2f(S[nt][2] - mn1);
                float p3 = ex2f(S[nt][3] - mn1);
                l0 += p0 + p1; l1 += p2 + p3;
                S[nt][0] = p0; S[nt][1] = p1; S[nt][2] = p2; S[nt][3] = p3;
            }
            // ---- PV: P 2-split x V 2-split, 3 products
            const uint32_t voff = (uint32_t)((lane & 15) * STRIDE + (lane >> 4) * 8) * 2u;
#pragma unroll
            for (int ks = 0; ks < 4; ks++) {
                uint32_t ah[4], al[4];
#pragma unroll
                for (int i = 0; i < 2; i++) {
                    int nt = 2 * ks + i;
                    uint32_t uh0; PACK_BF16X2(uh0, S[nt][0], S[nt][1]);
                    uint32_t uh1; PACK_BF16X2(uh1, S[nt][2], S[nt][3]);
                    float a0 = S[nt][0] - bf_lo(uh0), a1 = S[nt][1] - bf_hi(uh0);
                    float a2 = S[nt][2] - bf_lo(uh1), a3 = S[nt][3] - bf_hi(uh1);
                    uint32_t ul0; PACK_BF16X2(ul0, a0, a1);
                    uint32_t ul1; PACK_BF16X2(ul1, a2, a3);
                    ah[2 * i] = uh0; ah[2 * i + 1] = uh1;
                    al[2 * i] = ul0; al[2 * i + 1] = ul1;
                }
#pragma unroll
                for (int dg = 0; dg < 4; dg++) {
                    uint32_t base = (uint32_t)(ks * 16 * STRIDE + dg * 16) * 2u + voff;
                    uint32_t vh[4], vl[4];
                    LDMATRIX_X4_T(vh[0], vh[1], vh[2], vh[3], vh_p + base);
                    LDMATRIX_X4_T(vl[0], vl[1], vl[2], vl[3], vl_p + base);
                    MMA_BF16(O[2 * dg],     ah, vh[0], vh[1]);
                    MMA_BF16(O[2 * dg + 1], ah, vh[2], vh[3]);
                    MMA_BF16(O[2 * dg],     al, vh[0], vh[1]);
                    MMA_BF16(O[2 * dg + 1], al, vh[2], vh[3]);
                    MMA_BF16(O[2 * dg],     ah, vl[0], vl[1]);
                    MMA_BF16(O[2 * dg + 1], ah, vl[2], vl[3]);
                }
            }
        }
        __syncthreads();
    }

    // ---- epilogue
    l0 += __shfl_xor_sync(0xffffffffu, l0, 1);
    l0 += __shfl_xor_sync(0xffffffffu, l0, 2);
    l1 += __shfl_xor_sync(0xffffffffu, l1, 1);
    l1 += __shfl_xor_sync(0xffffffffu, l1, 2);
    float inv0 = 1.0f / l0, inv1 = 1.0f / l1;

    const size_t gr0 = (size_t)n * Lq + rbase + (lane >> 2);
#pragma unroll
    for (int nt = 0; nt < 8; nt++) {
        int col = nt * 8 + (lane & 3) * 2;
        float2 v0 = {O[nt][0] * inv0, O[nt][1] * inv0};
        float2 v1 = {O[nt][2] * inv1, O[nt][3] * inv1};
        *(float2*)(out + gr0 * Dh + col)       = v0;
        *(float2*)(out + (gr0 + 8) * Dh + col) = v1;
    }
}

extern "C" void kernel_launch(void* const* d_in, const int* in_sizes, int n_in,
                              void* d_out, int out_size) {
    const float* q  = (const float*)d_in[0];
    const float* k  = (const float*)d_in[1];
    const float* v  = (const float*)d_in[2];
    const float* Wq = (const float*)d_in[3];
    const float* Wk = (const float*)d_in[4];
    const float* Wv = (const float*)d_in[5];
    float* out = (float*)d_out;

    float* qh;
    cudaGetSymbolAddress((void**)&qh, g_qh);

    const int smem_attn = NBUF * NPLANE * PLANE_B;   // 147456 B
    cudaFuncSetAttribute(attn_mma, cudaFuncAttributeMaxDynamicSharedMemorySize, smem_attn);

    dim3 wgrid((Ein * Dh / 2) / 256, 3);
    prep_w<<<wgrid, 256>>>(Wq, Wk, Wv);

    dim3 pgrid((Nb * Lq) / 128, 3);
    proj_mma<<<pgrid, 256>>>(q, k, v, qh);

    dim3 grid(16, Nb);
    attn_mma<<<grid, 256, smem_attn>>>(out);
}